// round 8
// baseline (speedup 1.0000x reference)
#include <cuda_runtime.h>
#include <cuda_fp16.h>
#include <math.h>
#include <stdint.h>

#define F_ 2
#define V_ 4
#define FV 8
#define E_ 2048
#define NI 512
#define NO 512
#define M_ 514
#define GMIN 0.01f
#define GMAX 10.0f
#define PGMIN 1e-4f
#define ASCALE 16.0f
#define HSCALE 2048.0f
#define UINV (1.0f / 32768.0f)

// ---------------- scratch ------------------------------------------------------
__device__ __align__(16) unsigned short d_Ah[FV * E_ * NI];   // x fp16 [fv][e][k]
__device__ __align__(16) unsigned short d_Bw[FV * NO * NI];   // W fp16 [fv][n][k]
__device__ __align__(16) unsigned char  d_A8[FV * E_ * NI];   // 16*x e4m3
__device__ __align__(16) unsigned char  d_H8[FV * NO * NI];   // 2048*H e4m3
__device__ float d_gtilde[M_ * NO];
__device__ float d_G[NO];
__device__ float d_gsumm[M_];
__device__ float d_denp[FV * 32 * NO];
__device__ float d_invden[FV * NO];
__device__ float d_fixz[FV * NO];
__device__ float d_fixu[FV * NO];
__device__ float4 d_actp[NO];
__device__ float d_p1p[FV * 64];
__device__ float d_pwp[512];

__constant__ float c_etas[16] = {
    0.05f, 0.90f, 0.20f, 8.0f,
    0.10f, 0.80f, 0.30f, 5.0f,
    0.00f, 1.00f, 0.25f, 10.0f,
    0.15f, 0.70f, 0.15f, 6.0f};

__device__ __forceinline__ float th_clip(float t) {
    return fminf(fmaxf(t, -GMAX), GMAX);
}
__device__ __forceinline__ float th_fwd(float t) {
    float c = th_clip(t);
    return (fabsf(c) < GMIN) ? 0.0f : c;
}

// ---------------- PTX helpers (base ISA only) -----------------------------------
__device__ __forceinline__ uint32_t smem_to_u32(const void* p) {
    uint32_t a;
    asm("{ .reg .u64 t; cvta.to.shared.u64 t, %1; cvt.u32.u64 %0, t; }" : "=r"(a) : "l"(p));
    return a;
}
__device__ __forceinline__ uint32_t packh2(float hi, float lo) {
    uint32_t r;
    asm("cvt.rn.f16x2.f32 %0, %1, %2;" : "=r"(r) : "f"(hi), "f"(lo));
    return r;
}
__device__ __forceinline__ unsigned short packe4m3(float hi, float lo) {
    unsigned short r;
    asm("cvt.rn.satfinite.e4m3x2.f32 %0, %1, %2;" : "=h"(r) : "f"(hi), "f"(lo));
    return r;
}
__device__ __forceinline__ void cp_async16(uint32_t s, const void* g) {
    asm volatile("cp.async.cg.shared.global [%0], [%1], 16;" :: "r"(s), "l"(g) : "memory");
}
#define CP_COMMIT() asm volatile("cp.async.commit_group;" ::: "memory")
#define CP_WAIT1()  asm volatile("cp.async.wait_group 1;" ::: "memory")
#define CP_WAIT0()  asm volatile("cp.async.wait_group 0;" ::: "memory")

__device__ __forceinline__ void ldm4(uint32_t r[4], uint32_t addr) {
    asm volatile("ldmatrix.sync.aligned.m8n8.x4.shared.b16 {%0,%1,%2,%3}, [%4];"
                 : "=r"(r[0]), "=r"(r[1]), "=r"(r[2]), "=r"(r[3]) : "r"(addr));
}
__device__ __forceinline__ void mma_f16(float c[4], const uint32_t a[4],
                                        uint32_t b0, uint32_t b1) {
    asm volatile(
        "mma.sync.aligned.m16n8k16.row.col.f32.f16.f16.f32 "
        "{%0,%1,%2,%3}, {%4,%5,%6,%7}, {%8,%9}, {%0,%1,%2,%3};"
        : "+f"(c[0]), "+f"(c[1]), "+f"(c[2]), "+f"(c[3])
        : "r"(a[0]), "r"(a[1]), "r"(a[2]), "r"(a[3]), "r"(b0), "r"(b1));
}
__device__ __forceinline__ void mma_e4m3(float c[4], const uint32_t a[4],
                                         uint32_t b0, uint32_t b1) {
    asm volatile(
        "mma.sync.aligned.m16n8k32.row.col.f32.e4m3.e4m3.f32 "
        "{%0,%1,%2,%3}, {%4,%5,%6,%7}, {%8,%9}, {%0,%1,%2,%3};"
        : "+f"(c[0]), "+f"(c[1]), "+f"(c[2]), "+f"(c[3])
        : "r"(a[0]), "r"(a[1]), "r"(a[2]), "r"(a[3]), "r"(b0), "r"(b1));
}

// ---------------- g_tilde, G (+ fused activation select) -------------------------
__global__ void k_gtilde(const float* __restrict__ theta,
                         const float* __restrict__ coef,
                         const float* __restrict__ gum) {
    int n = blockIdx.x;
    int t = threadIdx.x;
    __shared__ float red[128];
    float mn = 1e30f;
    for (int m = t; m < M_; m += 128)
        mn = fminf(mn, fabsf(th_clip(theta[m * NO + n])));
    red[t] = mn;
    __syncthreads();
    for (int s = 64; s > 0; s >>= 1) {
        if (t < s) red[t] = fminf(red[t], red[t + s]);
        __syncthreads();
    }
    float scale = PGMIN / red[0];
    __syncthreads();
    float sum = 0.f;
    for (int m = t; m < M_; m += 128) {
        float g = fabsf(th_clip(theta[m * NO + n])) * scale;
        d_gtilde[m * NO + n] = g;
        sum += g;
    }
    red[t] = sum;
    __syncthreads();
    for (int s = 64; s > 0; s >>= 1) {
        if (t < s) red[t] += red[t + s];
        __syncthreads();
    }
    if (t == 0) {
        d_G[n] = red[0];
        float best = -1e30f;
        int bi = 0;
#pragma unroll
        for (int i = 0; i < 4; i++) {
            float c = fminf(fmaxf(coef[i * NO + n], -1.f), 1.f);
            float g = gum[i * NO + n];
            float gn = -logf(-logf(g + 1e-20f) + 1e-20f);
            float v = c + gn;
            if (v > best) { best = v; bi = i; }
        }
        d_actp[n] = make_float4(c_etas[bi * 4 + 0], c_etas[bi * 4 + 1],
                                c_etas[bi * 4 + 2], c_etas[bi * 4 + 3]);
    }
}

__global__ void k_gsumm() {
    int m = blockIdx.x;
    int t = threadIdx.x;
    __shared__ float red[128];
    float s = 0.f;
    for (int n = t; n < NO; n += 128) s += d_gtilde[m * NO + n];
    red[t] = s;
    __syncthreads();
    for (int k = 64; k > 0; k >>= 1) {
        if (t < k) red[t] += red[t + k];
        __syncthreads();
    }
    if (t == 0) d_gsumm[m] = red[0];
}

// ---------------- denominator partials ------------------------------------------
__global__ void k_denp(const float* __restrict__ theta, const float* __restrict__ nu) {
    int n = blockIdx.y * 256 + threadIdx.x;
    int bx = blockIdx.x;
    int fv = blockIdx.z;
    int m0 = bx * 17, m1 = min(M_, m0 + 17);
    float acc = 0.f;
#pragma unroll 17
    for (int m = m0; m < m1; m++) {
        float t = th_fwd(theta[m * NO + n]);
        float u = nu[((size_t)fv * M_ + m) * NO + n];
        acc += fabsf(t * (u * 0.2f + 0.9f));
    }
    d_denp[((size_t)fv * 32 + bx) * NO + n] = acc;
}

// ---------------- invden + exact fp32 fix rows (m = 512) ------------------------
__global__ void k_fix(const float* __restrict__ theta, const float* __restrict__ nu) {
    int fv = blockIdx.x;
    int n = blockIdx.y * 128 + threadIdx.x;
    float den = 1e-10f;
#pragma unroll
    for (int i = 0; i < 32; i++) den += d_denp[((size_t)fv * 32 + i) * NO + n];
    float inv = 1.f / den;
    d_invden[fv * NO + n] = inv;
    float th = th_fwd(theta[512 * NO + n]);
    float u = nu[((size_t)fv * M_ + 512) * NO + n];
    float tn = th * (u * 0.2f + 0.9f);
    d_fixz[fv * NO + n] = tn * inv;
    d_fixu[fv * NO + n] = d_gtilde[512 * NO + n] * (tn >= 0.f ? 1.f : -1.f);
}

// ---------------- B prep: W fp16 + H fp8, transposed to [n][k] --------------------
__global__ void k_prepB(const float* __restrict__ theta, const float* __restrict__ nu) {
    __shared__ float sw[64][65], sh[64][65];
    int t = threadIdx.x;
    int mt = blockIdx.x * 64, nt = blockIdx.y * 64, fv = blockIdx.z;
    int nl = t & 63;
    float inv = d_invden[fv * NO + nt + nl];
#pragma unroll 4
    for (int r = 0; r < 16; r++) {
        int ml = (t >> 6) * 16 + r;
        int m = mt + ml, n = nt + nl;
        float th = th_fwd(theta[m * NO + n]);
        float u = nu[((size_t)fv * M_ + m) * NO + n];
        float w = th * (u * 0.2f + 0.9f) * inv;
        sw[ml][nl] = w;
        sh[ml][nl] = d_gtilde[m * NO + n] * (w >= 0.f ? 1.f : -1.f);
    }
    __syncthreads();
    int nr = t >> 2, q = t & 3;
#pragma unroll
    for (int hf = 0; hf < 2; hf++) {
        float wv[8], hv[8];
#pragma unroll
        for (int j = 0; j < 8; j++) {
            wv[j] = sw[q * 16 + hf * 8 + j][nr];
            hv[j] = sh[q * 16 + hf * 8 + j][nr];
        }
        uint32_t hw[4];
#pragma unroll
        for (int p = 0; p < 4; p++)
            hw[p] = packh2(wv[2 * p + 1], wv[2 * p]);
        unsigned short q0 = packe4m3(hv[1] * HSCALE, hv[0] * HSCALE);
        unsigned short q1 = packe4m3(hv[3] * HSCALE, hv[2] * HSCALE);
        unsigned short q2 = packe4m3(hv[5] * HSCALE, hv[4] * HSCALE);
        unsigned short q3 = packe4m3(hv[7] * HSCALE, hv[6] * HSCALE);
        size_t eoff = ((size_t)fv * NO + nt + nr) * NI + mt + q * 16 + hf * 8;
        *(uint4*)((char*)d_Bw + eoff * 2) = make_uint4(hw[0], hw[1], hw[2], hw[3]);
        *(uint2*)((char*)d_H8 + eoff) =
            make_uint2((uint32_t)q0 | ((uint32_t)q1 << 16),
                       (uint32_t)q2 | ((uint32_t)q3 << 16));
    }
}

// ---------------- A prep: fp16 + fp8 + fused p1 partial ---------------------------
__global__ void k_prepA(const float* __restrict__ a) {
    __shared__ float gs[NI];
    __shared__ float red[256];
    int t = threadIdx.x;
    int ec = blockIdx.x, fv = blockIdx.y;   // 64 chunks of 32 rows
    for (int i = t; i < NI; i += 256) gs[i] = d_gsumm[i];
    __syncthreads();
    size_t base = ((size_t)fv * E_ + ec * 32) * NI;
    const float* ab = a + base;
    float acc = 0.f;
#pragma unroll 4
    for (int j = 0; j < 16; j++) {
        int flat = j * 256 + t;
        int e = flat >> 7, c4 = flat & 127;
        size_t off = (size_t)e * NI + c4 * 4;
        float4 x = *(const float4*)(ab + off);
        acc += x.x * x.x * gs[c4 * 4 + 0] + x.y * x.y * gs[c4 * 4 + 1] +
               x.z * x.z * gs[c4 * 4 + 2] + x.w * x.w * gs[c4 * 4 + 3];
        uint32_t h0 = packh2(x.y, x.x);
        uint32_t h1 = packh2(x.w, x.z);
        *(uint2*)((char*)d_Ah + (base + off) * 2) = make_uint2(h0, h1);
        unsigned short e0 = packe4m3(x.y * ASCALE, x.x * ASCALE);
        unsigned short e1 = packe4m3(x.w * ASCALE, x.z * ASCALE);
        *(uint32_t*)((char*)d_A8 + base + off) = (uint32_t)e0 | ((uint32_t)e1 << 16);
    }
    red[t] = acc;
    __syncthreads();
    for (int s = 128; s > 0; s >>= 1) {
        if (t < s) red[t] += red[t + s];
        __syncthreads();
    }
    if (t == 0) d_p1p[fv * 64 + ec] = red[0];
}

// ---------------- main mma GEMM ---------------------------------------------------
// CTA 128(E) x 128(N); 16 warps = 4(m) x 4(n); warp 32x32.
// k-chunks of 64: Z in fp16 (4 ks16), U in fp8 (2 ks32). 3 stages.
#define ROW16 144
#define ROW8  80
#define M16B  18432
#define M8B   10240
#define OFF_W  18432
#define OFF_A8 36864
#define OFF_H8 47104
#define STAGEB 57344

__global__ void __launch_bounds__(512, 1)
k_gemm(float* __restrict__ out) {
    extern __shared__ __align__(16) char dsm[];
    uint32_t sb = smem_to_u32(dsm);
    int t = threadIdx.x;
    int wid = t >> 5, lane = t & 31;
    int wm = wid & 3, wn = wid >> 2;
    int fv = blockIdx.z, e0 = blockIdx.y * 128, n0 = blockIdx.x * 128;

    const char* gA  = (const char*)d_Ah + ((size_t)fv * E_ + e0) * NI * 2;
    const char* gW  = (const char*)d_Bw + ((size_t)fv * NO + n0) * NI * 2;
    const char* gA8 = (const char*)d_A8 + ((size_t)fv * E_ + e0) * NI;
    const char* gH8 = (const char*)d_H8 + ((size_t)fv * NO + n0) * NI;

    int r16 = t >> 3, j16 = t & 7;       // fp16: 2 iterations of 512
    int r8 = t >> 2, j8 = t & 3;         // fp8: 1 iteration
    auto load_chunk = [&](int c, uint32_t base) {
#pragma unroll
        for (int it = 0; it < 2; it++) {
            int row = r16 + it * 64;
            uint32_t s = base + row * ROW16 + j16 * 16;
            size_t g = (size_t)row * 1024 + (size_t)c * 128 + j16 * 16;
            cp_async16(s, gA + g);
            cp_async16(s + OFF_W, gW + g);
        }
        uint32_t s8 = base + r8 * ROW8 + j8 * 16;
        size_t g8 = (size_t)r8 * 512 + (size_t)c * 64 + j8 * 16;
        cp_async16(s8 + OFF_A8, gA8 + g8);
        cp_async16(s8 + OFF_H8, gH8 + g8);
    };

    float zc[2][4][4], uc[2][4][4];
#pragma unroll
    for (int i = 0; i < 2; i++)
#pragma unroll
        for (int j = 0; j < 4; j++)
#pragma unroll
            for (int k = 0; k < 4; k++) { zc[i][j][k] = 0.f; uc[i][j][k] = 0.f; }

    uint32_t aoff  = (wm * 32 + (lane & 15)) * ROW16 + (lane >> 4) * 16;
    uint32_t boff  = (wn * 32 + (lane & 15)) * ROW16 + (lane >> 4) * 16;
    uint32_t aoff8 = (wm * 32 + (lane & 15)) * ROW8 + (lane >> 4) * 16;
    uint32_t boff8 = (wn * 32 + (lane & 15)) * ROW8 + (lane >> 4) * 16;

    load_chunk(0, sb);          CP_COMMIT();
    load_chunk(1, sb + STAGEB); CP_COMMIT();

    for (int c = 0; c < 8; c++) {
        uint32_t base = sb + (uint32_t)(c % 3) * STAGEB;
        if (c < 7) { CP_WAIT1(); } else { CP_WAIT0(); }
        __syncthreads();
        if (c + 2 < 8) {
            load_chunk(c + 2, sb + (uint32_t)((c + 2) % 3) * STAGEB);
            CP_COMMIT();
        }
        // ---- Z: fp16, 4 k16 steps ----
#pragma unroll
        for (int ks = 0; ks < 4; ks++) {
            uint32_t ah[2][4];
#pragma unroll
            for (int mt = 0; mt < 2; mt++)
                ldm4(ah[mt], base + aoff + mt * (16 * ROW16) + ks * 32);
            uint32_t bw[2][4];
#pragma unroll
            for (int pp = 0; pp < 2; pp++)
                ldm4(bw[pp], base + OFF_W + boff + pp * (16 * ROW16) + ks * 32);
#pragma unroll
            for (int mt = 0; mt < 2; mt++)
#pragma unroll
                for (int nt = 0; nt < 4; nt++) {
                    int pp = nt >> 1, s = nt & 1;
                    mma_f16(zc[mt][nt], ah[mt], bw[pp][s], bw[pp][s + 2]);
                }
        }
        // ---- U: fp8, 2 k32 steps ----
#pragma unroll
        for (int ks = 0; ks < 2; ks++) {
            uint32_t a8[2][4];
#pragma unroll
            for (int mt = 0; mt < 2; mt++)
                ldm4(a8[mt], base + OFF_A8 + aoff8 + mt * (16 * ROW8) + ks * 32);
            uint32_t h8[2][4];
#pragma unroll
            for (int pp = 0; pp < 2; pp++)
                ldm4(h8[pp], base + OFF_H8 + boff8 + pp * (16 * ROW8) + ks * 32);
#pragma unroll
            for (int mt = 0; mt < 2; mt++)
#pragma unroll
                for (int nt = 0; nt < 4; nt++) {
                    int pp = nt >> 1, s = nt & 1;
                    mma_e4m3(uc[mt][nt], a8[mt], h8[pp][s], h8[pp][s + 2]);
                }
        }
    }

    // ---------------- epilogue ----------------
    float pw = 0.f;
    int lrow = lane >> 2, lcol = (lane & 3) * 2;
#pragma unroll
    for (int nt = 0; nt < 4; nt++) {
        int nc = n0 + wn * 32 + nt * 8 + lcol;
        float fz0 = d_fixz[fv * NO + nc],     fz1 = d_fixz[fv * NO + nc + 1];
        float fu0 = d_fixu[fv * NO + nc],     fu1 = d_fixu[fv * NO + nc + 1];
        float G0  = d_G[nc],                  G1  = d_G[nc + 1];
        float4 P0 = d_actp[nc],               P1  = d_actp[nc + 1];
#pragma unroll
        for (int mt = 0; mt < 2; mt++) {
            int r0 = e0 + wm * 32 + mt * 16 + lrow;
#pragma unroll
            for (int h = 0; h < 2; h++) {
                float z0 = zc[mt][nt][2 * h + 0] + fz0;
                float z1 = zc[mt][nt][2 * h + 1] + fz1;
                float u0 = uc[mt][nt][2 * h + 0] * UINV + fu0;
                float u1 = uc[mt][nt][2 * h + 1] * UINV + fu1;
                pw += z0 * (z0 * G0 - 2.f * u0);
                pw += z1 * (z1 * G1 - 2.f * u1);
                float2 o;
                o.x = P0.x + P0.y * tanhf((z0 - P0.z) * P0.w);
                o.y = P1.x + P1.y * tanhf((z1 - P1.z) * P1.w);
                *(float2*)(out + ((size_t)fv * E_ + r0 + h * 8) * NO + nc) = o;
            }
        }
    }

    __shared__ float red[512];
    red[t] = pw;
    __syncthreads();
    for (int s = 256; s > 0; s >>= 1) {
        if (t < s) red[t] += red[t + s];
        __syncthreads();
    }
    if (t == 0)
        d_pwp[(blockIdx.z * 4 + blockIdx.x) * 16 + blockIdx.y] = red[0];
}

// ---------------- final ----------------------------------------------------------
__global__ void k_final(float* __restrict__ out, int out_size) {
    __shared__ float red[256];
    int t = threadIdx.x;
    float s = 0.f;
    for (int i = t; i < 512; i += 256) s += d_pwp[i];
    for (int i = t; i < FV * 64; i += 256) s += d_p1p[i];
    red[t] = s;
    __syncthreads();
    for (int k = 128; k > 0; k >>= 1) {
        if (t < k) red[t] += red[t + k];
        __syncthreads();
    }
    if (t == 0) {
        float p1_ones = (float)(FV * E_) * d_gsumm[512];
        float power = (red[0] + p1_ones) / (float)(E_ * V_ * F_);
        long long total = (long long)FV * E_ * NO;
        if (out_size > total) out[total] = power;
    }
}

extern "C" void kernel_launch(void* const* d_in, const int* in_sizes, int n_in,
                              void* d_out, int out_size) {
    const float* a     = (const float*)d_in[0];
    const float* theta = (const float*)d_in[1];
    const float* coef  = (const float*)d_in[2];
    const float* nu    = (const float*)d_in[3];
    const float* gum   = (const float*)d_in[4];
    float* out = (float*)d_out;
    (void)in_sizes; (void)n_in;

    static int smem_set = 0;
    if (!smem_set) {
        cudaFuncSetAttribute(k_gemm, cudaFuncAttributeMaxDynamicSharedMemorySize,
                             3 * STAGEB);
        smem_set = 1;
    }

    k_gtilde<<<NO, 128>>>(theta, coef, gum);
    k_gsumm<<<M_, 128>>>();
    k_denp<<<dim3(32, 2, FV), 256>>>(theta, nu);
    k_fix<<<dim3(FV, 4), 128>>>(theta, nu);
    k_prepB<<<dim3(8, 8, FV), 256>>>(theta, nu);
    k_prepA<<<dim3(64, FV), 256>>>(a);
    k_gemm<<<dim3(4, 16, FV), 512, 3 * STAGEB>>>(out);
    k_final<<<1, 256>>>(out, out_size);
}

// round 9
// speedup vs baseline: 1.2123x; 1.2123x over previous
#include <cuda_runtime.h>
#include <cuda_fp16.h>
#include <math.h>
#include <stdint.h>

#define F_ 2
#define V_ 4
#define FV 8
#define E_ 2048
#define NI 512
#define NO 512
#define M_ 514
#define GMIN 0.01f
#define GMAX 10.0f
#define PGMIN 1e-4f

// ---------------- scratch ------------------------------------------------------
__device__ __align__(16) unsigned short d_Ah[FV * E_ * NI];   // x fp16 [fv][e][k]
__device__ __align__(16) unsigned short d_Bw[FV * NO * NI];   // W fp16 [fv][n][k]
__device__ __align__(16) unsigned short d_Hb[FV * NO * NI];   // H fp16 [fv][n][k]
__device__ float d_gtilde[M_ * NO];
__device__ float d_G[NO];
__device__ float d_gsumm[M_];
__device__ float d_denp[FV * 32 * NO];
__device__ float d_fixz[FV * NO];
__device__ float d_fixu[FV * NO];
__device__ float4 d_actp[NO];
__device__ float d_p1p[FV * 64];
__device__ float d_pwp[512];

__constant__ float c_etas[16] = {
    0.05f, 0.90f, 0.20f, 8.0f,
    0.10f, 0.80f, 0.30f, 5.0f,
    0.00f, 1.00f, 0.25f, 10.0f,
    0.15f, 0.70f, 0.15f, 6.0f};

__device__ __forceinline__ float th_clip(float t) {
    return fminf(fmaxf(t, -GMAX), GMAX);
}
__device__ __forceinline__ float th_fwd(float t) {
    float c = th_clip(t);
    return (fabsf(c) < GMIN) ? 0.0f : c;
}

// ---------------- PTX helpers (base ISA only) -----------------------------------
__device__ __forceinline__ uint32_t smem_to_u32(const void* p) {
    uint32_t a;
    asm("{ .reg .u64 t; cvta.to.shared.u64 t, %1; cvt.u32.u64 %0, t; }" : "=r"(a) : "l"(p));
    return a;
}
__device__ __forceinline__ uint32_t packh2(float hi, float lo) {
    uint32_t r;
    asm("cvt.rn.f16x2.f32 %0, %1, %2;" : "=r"(r) : "f"(hi), "f"(lo));
    return r;
}
__device__ __forceinline__ void cp_async16(uint32_t s, const void* g) {
    asm volatile("cp.async.cg.shared.global [%0], [%1], 16;" :: "r"(s), "l"(g) : "memory");
}
#define CP_COMMIT() asm volatile("cp.async.commit_group;" ::: "memory")
#define CP_WAIT1()  asm volatile("cp.async.wait_group 1;" ::: "memory")
#define CP_WAIT0()  asm volatile("cp.async.wait_group 0;" ::: "memory")

__device__ __forceinline__ void ldm4(uint32_t r[4], uint32_t addr) {
    asm volatile("ldmatrix.sync.aligned.m8n8.x4.shared.b16 {%0,%1,%2,%3}, [%4];"
                 : "=r"(r[0]), "=r"(r[1]), "=r"(r[2]), "=r"(r[3]) : "r"(addr));
}
__device__ __forceinline__ void mma_f16(float c[4], const uint32_t a[4],
                                        uint32_t b0, uint32_t b1) {
    asm volatile(
        "mma.sync.aligned.m16n8k16.row.col.f32.f16.f16.f32 "
        "{%0,%1,%2,%3}, {%4,%5,%6,%7}, {%8,%9}, {%0,%1,%2,%3};"
        : "+f"(c[0]), "+f"(c[1]), "+f"(c[2]), "+f"(c[3])
        : "r"(a[0]), "r"(a[1]), "r"(a[2]), "r"(a[3]), "r"(b0), "r"(b1));
}

// ---------------- K1: fused denp (blocks 0..511) + gtilde/G/act (512..575) ------
__global__ void k_pre1(const float* __restrict__ theta,
                       const float* __restrict__ coef,
                       const float* __restrict__ gum,
                       const float* __restrict__ nu) {
    int b = blockIdx.x;
    int t = threadIdx.x;
    if (b < 512) {
        // denominator partials: 32 m-chunks x 2 n-halves x 8 fv
        int bx = b & 31;
        int yy = (b >> 5) & 1;
        int fv = b >> 6;
        int n = yy * 256 + t;
        int m0 = bx * 17, m1 = min(M_, m0 + 17);
        float acc = 0.f;
#pragma unroll 17
        for (int m = m0; m < m1; m++) {
            float th = th_fwd(theta[m * NO + n]);
            float u = nu[((size_t)fv * M_ + m) * NO + n];
            acc += fabsf(th * (u * 0.2f + 0.9f));
        }
        d_denp[((size_t)fv * 32 + bx) * NO + n] = acc;
    } else {
        // gtilde: one warp per output column
        int blk = b - 512;           // 0..63
        int w = t >> 5, lane = t & 31;
        int n = blk * 8 + w;
        float mn = 1e30f;
#pragma unroll
        for (int i = 0; i < 17; i++) {
            int m = lane + 32 * i;
            if (m < M_) mn = fminf(mn, fabsf(th_clip(theta[m * NO + n])));
        }
#pragma unroll
        for (int s = 16; s > 0; s >>= 1)
            mn = fminf(mn, __shfl_xor_sync(0xFFFFFFFFu, mn, s));
        float scale = PGMIN / mn;
        float sum = 0.f;
#pragma unroll
        for (int i = 0; i < 17; i++) {
            int m = lane + 32 * i;
            if (m < M_) {
                float g = fabsf(th_clip(theta[m * NO + n])) * scale;
                d_gtilde[m * NO + n] = g;
                sum += g;
            }
        }
#pragma unroll
        for (int s = 16; s > 0; s >>= 1)
            sum += __shfl_xor_sync(0xFFFFFFFFu, sum, s);
        if (lane == 0) {
            d_G[n] = sum;
            float best = -1e30f;
            int bi = 0;
#pragma unroll
            for (int i = 0; i < 4; i++) {
                float c = fminf(fmaxf(coef[i * NO + n], -1.f), 1.f);
                float g = gum[i * NO + n];
                float gn = -logf(-logf(g + 1e-20f) + 1e-20f);
                float v = c + gn;
                if (v > best) { best = v; bi = i; }
            }
            d_actp[n] = make_float4(c_etas[bi * 4 + 0], c_etas[bi * 4 + 1],
                                    c_etas[bi * 4 + 2], c_etas[bi * 4 + 3]);
        }
    }
}

// ---------------- K2: prepB (z<8, inline invden + fix on x==0) + gsumm (z==8) ----
__global__ void k_pre2(const float* __restrict__ theta, const float* __restrict__ nu) {
    int t = threadIdx.x;
    if (blockIdx.z == 8) {
        // gsumm: 64 blocks, warp-per-row (2 reps), rows idx*9 .. idx*9+8
        int idx = blockIdx.y * 8 + blockIdx.x;
        int w = t >> 5, lane = t & 31;
#pragma unroll
        for (int rep = 0; rep < 2; rep++) {
            int j = w + 8 * rep;
            int r = idx * 9 + j;
            if (j < 9 && r < M_) {
                float s = 0.f;
#pragma unroll
                for (int i = 0; i < 16; i++)
                    s += d_gtilde[r * NO + lane + 32 * i];
#pragma unroll
                for (int q = 16; q > 0; q >>= 1)
                    s += __shfl_xor_sync(0xFFFFFFFFu, s, q);
                if (lane == 0) d_gsumm[r] = s;
            }
        }
        return;
    }
    __shared__ float sw[64][65], sh[64][65];
    int mt = blockIdx.x * 64, nt = blockIdx.y * 64, fv = blockIdx.z;
    int nl = t & 63;
    // inline invden: sum the 32 denp partials for this column
    float den = 1e-10f;
#pragma unroll
    for (int i = 0; i < 32; i++)
        den += d_denp[((size_t)fv * 32 + i) * NO + nt + nl];
    float inv = 1.f / den;
#pragma unroll 4
    for (int r = 0; r < 16; r++) {
        int ml = (t >> 6) * 16 + r;
        int m = mt + ml, n = nt + nl;
        float th = th_fwd(theta[m * NO + n]);
        float u = nu[((size_t)fv * M_ + m) * NO + n];
        float w = th * (u * 0.2f + 0.9f) * inv;
        sw[ml][nl] = w;
        sh[ml][nl] = d_gtilde[m * NO + n] * (w >= 0.f ? 1.f : -1.f);
    }
    // fix row (m = 512), exact fp32, done once per (fv, n)
    if (blockIdx.x == 0 && t < 64) {
        int n = nt + t;
        float th = th_fwd(theta[512 * NO + n]);
        float u = nu[((size_t)fv * M_ + 512) * NO + n];
        float tn = th * (u * 0.2f + 0.9f);
        d_fixz[fv * NO + n] = tn * inv;   // t<64 -> nl==t, inv matches column n
        d_fixu[fv * NO + n] = d_gtilde[512 * NO + n] * (tn >= 0.f ? 1.f : -1.f);
    }
    __syncthreads();
    int nr = t >> 2, q = t & 3;
#pragma unroll
    for (int hf = 0; hf < 2; hf++) {
        float wv[8], hv[8];
#pragma unroll
        for (int j = 0; j < 8; j++) {
            wv[j] = sw[q * 16 + hf * 8 + j][nr];
            hv[j] = sh[q * 16 + hf * 8 + j][nr];
        }
        uint32_t hw[4], hb[4];
#pragma unroll
        for (int p = 0; p < 4; p++) {
            hw[p] = packh2(wv[2 * p + 1], wv[2 * p]);
            hb[p] = packh2(hv[2 * p + 1], hv[2 * p]);
        }
        size_t eoff = ((size_t)fv * NO + nt + nr) * NI + mt + q * 16 + hf * 8;
        *(uint4*)((char*)d_Bw + eoff * 2) = make_uint4(hw[0], hw[1], hw[2], hw[3]);
        *(uint4*)((char*)d_Hb + eoff * 2) = make_uint4(hb[0], hb[1], hb[2], hb[3]);
    }
}

// ---------------- K3: A prep fp16 + fused p1 partial ------------------------------
__global__ void k_prepA(const float* __restrict__ a) {
    __shared__ float gs[NI];
    __shared__ float red[256];
    int t = threadIdx.x;
    int ec = blockIdx.x, fv = blockIdx.y;   // 64 chunks of 32 rows
    for (int i = t; i < NI; i += 256) gs[i] = d_gsumm[i];
    __syncthreads();
    size_t base = ((size_t)fv * E_ + ec * 32) * NI;
    const float* ab = a + base;
    float acc = 0.f;
#pragma unroll 4
    for (int j = 0; j < 16; j++) {
        int flat = j * 256 + t;
        int e = flat >> 7, c4 = flat & 127;
        size_t off = (size_t)e * NI + c4 * 4;
        float4 x = *(const float4*)(ab + off);
        acc += x.x * x.x * gs[c4 * 4 + 0] + x.y * x.y * gs[c4 * 4 + 1] +
               x.z * x.z * gs[c4 * 4 + 2] + x.w * x.w * gs[c4 * 4 + 3];
        uint32_t h0 = packh2(x.y, x.x);
        uint32_t h1 = packh2(x.w, x.z);
        *(uint2*)((char*)d_Ah + (base + off) * 2) = make_uint2(h0, h1);
    }
    red[t] = acc;
    __syncthreads();
    for (int s = 128; s > 0; s >>= 1) {
        if (t < s) red[t] += red[t + s];
        __syncthreads();
    }
    if (t == 0) d_p1p[fv * 64 + ec] = red[0];
}

// ---------------- K4: main mma.sync GEMM -------------------------------------------
// CTA 128(E) x 128(N); 16 warps = 4(m) x 4(n); warp 32x32; k-chunks of 32, 3 stages.
#define ROWB 80
#define MATB 10240
#define STAGEB 30720

__global__ void __launch_bounds__(512, 1)
k_gemm(float* __restrict__ out) {
    extern __shared__ __align__(16) char dsm[];
    uint32_t sb = smem_to_u32(dsm);
    int t = threadIdx.x;
    int wid = t >> 5, lane = t & 31;
    int wm = wid & 3, wn = wid >> 2;
    int fv = blockIdx.z, e0 = blockIdx.y * 128, n0 = blockIdx.x * 128;

    const char* gA = (const char*)d_Ah + ((size_t)fv * E_ + e0) * NI * 2;
    const char* gB = (const char*)d_Bw + ((size_t)fv * NO + n0) * NI * 2;
    const char* gH = (const char*)d_Hb + ((size_t)fv * NO + n0) * NI * 2;

    int lrowc = t >> 2, lj = t & 3;
    auto load_chunk = [&](int c, uint32_t base) {
        uint32_t s = base + lrowc * ROWB + lj * 16;
        size_t g = (size_t)lrowc * 1024 + (size_t)c * 64 + lj * 16;
        cp_async16(s,            gA + g);
        cp_async16(s + MATB,     gB + g);
        cp_async16(s + 2 * MATB, gH + g);
    };

    float zc[2][4][4], uc[2][4][4];
#pragma unroll
    for (int i = 0; i < 2; i++)
#pragma unroll
        for (int j = 0; j < 4; j++)
#pragma unroll
            for (int k = 0; k < 4; k++) { zc[i][j][k] = 0.f; uc[i][j][k] = 0.f; }

    uint32_t aoff = (wm * 32 + (lane & 15)) * ROWB + (lane >> 4) * 16;
    uint32_t boff = (wn * 32 + (lane & 15)) * ROWB + (lane >> 4) * 16;

    load_chunk(0, sb);          CP_COMMIT();
    load_chunk(1, sb + STAGEB); CP_COMMIT();

    for (int c = 0; c < 16; c++) {
        uint32_t base = sb + (uint32_t)(c % 3) * STAGEB;
        if (c < 15) { CP_WAIT1(); } else { CP_WAIT0(); }
        __syncthreads();
        if (c + 2 < 16) {
            load_chunk(c + 2, sb + (uint32_t)((c + 2) % 3) * STAGEB);
            CP_COMMIT();
        }
#pragma unroll
        for (int ks = 0; ks < 2; ks++) {
            uint32_t ah[2][4];
#pragma unroll
            for (int mt = 0; mt < 2; mt++)
                ldm4(ah[mt], base + aoff + mt * (16 * ROWB) + ks * 32);
            uint32_t bw[2][4], hb[2][4];
#pragma unroll
            for (int pp = 0; pp < 2; pp++) {
                uint32_t bd = base + MATB + boff + pp * (16 * ROWB) + ks * 32;
                ldm4(bw[pp], bd);
                ldm4(hb[pp], bd + MATB);
            }
#pragma unroll
            for (int mt = 0; mt < 2; mt++)
#pragma unroll
                for (int nt = 0; nt < 4; nt++) {
                    int pp = nt >> 1, s = nt & 1;
                    mma_f16(zc[mt][nt], ah[mt], bw[pp][s], bw[pp][s + 2]);
                    mma_f16(uc[mt][nt], ah[mt], hb[pp][s], hb[pp][s + 2]);
                }
        }
    }

    // ---------------- epilogue ----------------
    float pw = 0.f;
    int lrow = lane >> 2, lcol = (lane & 3) * 2;
#pragma unroll
    for (int nt = 0; nt < 4; nt++) {
        int nc = n0 + wn * 32 + nt * 8 + lcol;
        float fz0 = d_fixz[fv * NO + nc],     fz1 = d_fixz[fv * NO + nc + 1];
        float fu0 = d_fixu[fv * NO + nc],     fu1 = d_fixu[fv * NO + nc + 1];
        float G0  = d_G[nc],                  G1  = d_G[nc + 1];
        float4 P0 = d_actp[nc],               P1  = d_actp[nc + 1];
#pragma unroll
        for (int mt = 0; mt < 2; mt++) {
            int r0 = e0 + wm * 32 + mt * 16 + lrow;
#pragma unroll
            for (int h = 0; h < 2; h++) {
                float z0 = zc[mt][nt][2 * h + 0] + fz0;
                float z1 = zc[mt][nt][2 * h + 1] + fz1;
                float u0 = uc[mt][nt][2 * h + 0] + fu0;
                float u1 = uc[mt][nt][2 * h + 1] + fu1;
                pw += z0 * (z0 * G0 - 2.f * u0);
                pw += z1 * (z1 * G1 - 2.f * u1);
                float2 o;
                o.x = P0.x + P0.y * tanhf((z0 - P0.z) * P0.w);
                o.y = P1.x + P1.y * tanhf((z1 - P1.z) * P1.w);
                *(float2*)(out + ((size_t)fv * E_ + r0 + h * 8) * NO + nc) = o;
            }
        }
    }

    __shared__ float red[512];
    red[t] = pw;
    __syncthreads();
    for (int s = 256; s > 0; s >>= 1) {
        if (t < s) red[t] += red[t + s];
        __syncthreads();
    }
    if (t == 0)
        d_pwp[(blockIdx.z * 4 + blockIdx.x) * 16 + blockIdx.y] = red[0];
}

// ---------------- K5: final --------------------------------------------------------
__global__ void k_final(float* __restrict__ out, int out_size) {
    __shared__ float red[256];
    int t = threadIdx.x;
    float s = 0.f;
    for (int i = t; i < 512; i += 256) s += d_pwp[i];
    for (int i = t; i < FV * 64; i += 256) s += d_p1p[i];
    red[t] = s;
    __syncthreads();
    for (int k = 128; k > 0; k >>= 1) {
        if (t < k) red[t] += red[t + k];
        __syncthreads();
    }
    if (t == 0) {
        float p1_ones = (float)(FV * E_) * d_gsumm[512];
        float power = (red[0] + p1_ones) / (float)(E_ * V_ * F_);
        long long total = (long long)FV * E_ * NO;
        if (out_size > total) out[total] = power;
    }
}

extern "C" void kernel_launch(void* const* d_in, const int* in_sizes, int n_in,
                              void* d_out, int out_size) {
    const float* a     = (const float*)d_in[0];
    const float* theta = (const float*)d_in[1];
    const float* coef  = (const float*)d_in[2];
    const float* nu    = (const float*)d_in[3];
    const float* gum   = (const float*)d_in[4];
    float* out = (float*)d_out;
    (void)in_sizes; (void)n_in;

    static int smem_set = 0;
    if (!smem_set) {
        cudaFuncSetAttribute(k_gemm, cudaFuncAttributeMaxDynamicSharedMemorySize,
                             3 * STAGEB);
        smem_set = 1;
    }

    k_pre1<<<576, 256>>>(theta, coef, gum, nu);
    k_pre2<<<dim3(8, 8, 9), 256>>>(theta, nu);
    k_prepA<<<dim3(64, FV), 256>>>(a);
    k_gemm<<<dim3(4, 16, FV), 512, 3 * STAGEB>>>(out);
    k_final<<<1, 256>>>(out, out_size);
}

// round 10
// speedup vs baseline: 1.2394x; 1.0224x over previous
#include <cuda_runtime.h>
#include <cuda_fp16.h>
#include <math.h>
#include <stdint.h>

#define F_ 2
#define V_ 4
#define FV 8
#define E_ 2048
#define NI 512
#define NO 512
#define M_ 514
#define GMIN 0.01f
#define GMAX 10.0f
#define PGMIN 1e-4f

// ---------------- scratch ------------------------------------------------------
__device__ __align__(16) unsigned short d_Ah[FV * E_ * NI];   // x fp16 [fv][e][k]
__device__ __align__(16) unsigned short d_Bw[FV * NO * NI];   // W fp16 [fv][n][k]
__device__ __align__(16) unsigned short d_Hb[FV * NO * NI];   // H fp16 [fv][n][k]
__device__ float d_gtilde[M_ * NO];
__device__ float d_G[NO];
__device__ float d_gsumm[M_];
__device__ float d_denp[FV * 32 * NO];
__device__ float d_fixz[FV * NO];
__device__ float d_fixu[FV * NO];
__device__ float4 d_actp[NO];
__device__ float d_p1p[FV * 64];
__device__ float d_pwp[512];

__constant__ float c_etas[16] = {
    0.05f, 0.90f, 0.20f, 8.0f,
    0.10f, 0.80f, 0.30f, 5.0f,
    0.00f, 1.00f, 0.25f, 10.0f,
    0.15f, 0.70f, 0.15f, 6.0f};

__device__ __forceinline__ float th_clip(float t) {
    return fminf(fmaxf(t, -GMAX), GMAX);
}
__device__ __forceinline__ float th_fwd(float t) {
    float c = th_clip(t);
    return (fabsf(c) < GMIN) ? 0.0f : c;
}

// ---------------- PTX helpers (base ISA only) -----------------------------------
__device__ __forceinline__ uint32_t smem_to_u32(const void* p) {
    uint32_t a;
    asm("{ .reg .u64 t; cvta.to.shared.u64 t, %1; cvt.u32.u64 %0, t; }" : "=r"(a) : "l"(p));
    return a;
}
__device__ __forceinline__ uint32_t packh2(float hi, float lo) {
    uint32_t r;
    asm("cvt.rn.f16x2.f32 %0, %1, %2;" : "=r"(r) : "f"(hi), "f"(lo));
    return r;
}
__device__ __forceinline__ void cp_async16(uint32_t s, const void* g) {
    asm volatile("cp.async.cg.shared.global [%0], [%1], 16;" :: "r"(s), "l"(g) : "memory");
}
#define CP_COMMIT() asm volatile("cp.async.commit_group;" ::: "memory")
#define CP_WAIT1()  asm volatile("cp.async.wait_group 1;" ::: "memory")
#define CP_WAIT0()  asm volatile("cp.async.wait_group 0;" ::: "memory")

__device__ __forceinline__ void ldm4(uint32_t r[4], uint32_t addr) {
    asm volatile("ldmatrix.sync.aligned.m8n8.x4.shared.b16 {%0,%1,%2,%3}, [%4];"
                 : "=r"(r[0]), "=r"(r[1]), "=r"(r[2]), "=r"(r[3]) : "r"(addr));
}
__device__ __forceinline__ void mma_f16(float c[4], const uint32_t a[4],
                                        uint32_t b0, uint32_t b1) {
    asm volatile(
        "mma.sync.aligned.m16n8k16.row.col.f32.f16.f16.f32 "
        "{%0,%1,%2,%3}, {%4,%5,%6,%7}, {%8,%9}, {%0,%1,%2,%3};"
        : "+f"(c[0]), "+f"(c[1]), "+f"(c[2]), "+f"(c[3])
        : "r"(a[0]), "r"(a[1]), "r"(a[2]), "r"(a[3]), "r"(b0), "r"(b1));
}

// ---------------- K1: fused denp (blocks 0..511) + gtilde/G/act (512..575) ------
__global__ void k_pre1(const float* __restrict__ theta,
                       const float* __restrict__ coef,
                       const float* __restrict__ gum,
                       const float* __restrict__ nu) {
    int b = blockIdx.x;
    int t = threadIdx.x;
    if (b < 512) {
        int bx = b & 31;
        int yy = (b >> 5) & 1;
        int fv = b >> 6;
        int n = yy * 256 + t;
        int m0 = bx * 17, m1 = min(M_, m0 + 17);
        float acc = 0.f;
#pragma unroll 17
        for (int m = m0; m < m1; m++) {
            float th = th_fwd(theta[m * NO + n]);
            float u = nu[((size_t)fv * M_ + m) * NO + n];
            acc += fabsf(th * (u * 0.2f + 0.9f));
        }
        d_denp[((size_t)fv * 32 + bx) * NO + n] = acc;
    } else {
        int blk = b - 512;
        int w = t >> 5, lane = t & 31;
        int n = blk * 8 + w;
        float mn = 1e30f;
#pragma unroll
        for (int i = 0; i < 17; i++) {
            int m = lane + 32 * i;
            if (m < M_) mn = fminf(mn, fabsf(th_clip(theta[m * NO + n])));
        }
#pragma unroll
        for (int s = 16; s > 0; s >>= 1)
            mn = fminf(mn, __shfl_xor_sync(0xFFFFFFFFu, mn, s));
        float scale = PGMIN / mn;
        float sum = 0.f;
#pragma unroll
        for (int i = 0; i < 17; i++) {
            int m = lane + 32 * i;
            if (m < M_) {
                float g = fabsf(th_clip(theta[m * NO + n])) * scale;
                d_gtilde[m * NO + n] = g;
                sum += g;
            }
        }
#pragma unroll
        for (int s = 16; s > 0; s >>= 1)
            sum += __shfl_xor_sync(0xFFFFFFFFu, sum, s);
        if (lane == 0) {
            d_G[n] = sum;
            float best = -1e30f;
            int bi = 0;
#pragma unroll
            for (int i = 0; i < 4; i++) {
                float c = fminf(fmaxf(coef[i * NO + n], -1.f), 1.f);
                float g = gum[i * NO + n];
                float gn = -logf(-logf(g + 1e-20f) + 1e-20f);
                float v = c + gn;
                if (v > best) { best = v; bi = i; }
            }
            d_actp[n] = make_float4(c_etas[bi * 4 + 0], c_etas[bi * 4 + 1],
                                    c_etas[bi * 4 + 2], c_etas[bi * 4 + 3]);
        }
    }
}

// ---------------- K2: prepB (z<8, inline invden + fix on x==0) + gsumm (z==8) ----
__global__ void k_pre2(const float* __restrict__ theta, const float* __restrict__ nu) {
    int t = threadIdx.x;
    if (blockIdx.z == 8) {
        int idx = blockIdx.y * 8 + blockIdx.x;
        int w = t >> 5, lane = t & 31;
#pragma unroll
        for (int rep = 0; rep < 2; rep++) {
            int j = w + 8 * rep;
            int r = idx * 9 + j;
            if (j < 9 && r < M_) {
                float s = 0.f;
#pragma unroll
                for (int i = 0; i < 16; i++)
                    s += d_gtilde[r * NO + lane + 32 * i];
#pragma unroll
                for (int q = 16; q > 0; q >>= 1)
                    s += __shfl_xor_sync(0xFFFFFFFFu, s, q);
                if (lane == 0) d_gsumm[r] = s;
            }
        }
        return;
    }
    __shared__ float sw[64][65], sh[64][65];
    int mt = blockIdx.x * 64, nt = blockIdx.y * 64, fv = blockIdx.z;
    int nl = t & 63;
    float den = 1e-10f;
#pragma unroll
    for (int i = 0; i < 32; i++)
        den += d_denp[((size_t)fv * 32 + i) * NO + nt + nl];
    float inv = 1.f / den;
#pragma unroll 4
    for (int r = 0; r < 16; r++) {
        int ml = (t >> 6) * 16 + r;
        int m = mt + ml, n = nt + nl;
        float th = th_fwd(theta[m * NO + n]);
        float u = nu[((size_t)fv * M_ + m) * NO + n];
        float w = th * (u * 0.2f + 0.9f) * inv;
        sw[ml][nl] = w;
        sh[ml][nl] = d_gtilde[m * NO + n] * (w >= 0.f ? 1.f : -1.f);
    }
    if (blockIdx.x == 0 && t < 64) {
        int n = nt + t;
        float th = th_fwd(theta[512 * NO + n]);
        float u = nu[((size_t)fv * M_ + 512) * NO + n];
        float tn = th * (u * 0.2f + 0.9f);
        d_fixz[fv * NO + n] = tn * inv;
        d_fixu[fv * NO + n] = d_gtilde[512 * NO + n] * (tn >= 0.f ? 1.f : -1.f);
    }
    __syncthreads();
    int nr = t >> 2, q = t & 3;
#pragma unroll
    for (int hf = 0; hf < 2; hf++) {
        float wv[8], hv[8];
#pragma unroll
        for (int j = 0; j < 8; j++) {
            wv[j] = sw[q * 16 + hf * 8 + j][nr];
            hv[j] = sh[q * 16 + hf * 8 + j][nr];
        }
        uint32_t hw[4], hb[4];
#pragma unroll
        for (int p = 0; p < 4; p++) {
            hw[p] = packh2(wv[2 * p + 1], wv[2 * p]);
            hb[p] = packh2(hv[2 * p + 1], hv[2 * p]);
        }
        size_t eoff = ((size_t)fv * NO + nt + nr) * NI + mt + q * 16 + hf * 8;
        *(uint4*)((char*)d_Bw + eoff * 2) = make_uint4(hw[0], hw[1], hw[2], hw[3]);
        *(uint4*)((char*)d_Hb + eoff * 2) = make_uint4(hb[0], hb[1], hb[2], hb[3]);
    }
}

// ---------------- K3: A prep fp16 + fused p1 partial ------------------------------
__global__ void k_prepA(const float* __restrict__ a) {
    __shared__ float gs[NI];
    __shared__ float red[256];
    int t = threadIdx.x;
    int ec = blockIdx.x, fv = blockIdx.y;
    for (int i = t; i < NI; i += 256) gs[i] = d_gsumm[i];
    __syncthreads();
    size_t base = ((size_t)fv * E_ + ec * 32) * NI;
    const float* ab = a + base;
    float acc = 0.f;
#pragma unroll 4
    for (int j = 0; j < 16; j++) {
        int flat = j * 256 + t;
        int e = flat >> 7, c4 = flat & 127;
        size_t off = (size_t)e * NI + c4 * 4;
        float4 x = *(const float4*)(ab + off);
        acc += x.x * x.x * gs[c4 * 4 + 0] + x.y * x.y * gs[c4 * 4 + 1] +
               x.z * x.z * gs[c4 * 4 + 2] + x.w * x.w * gs[c4 * 4 + 3];
        uint32_t h0 = packh2(x.y, x.x);
        uint32_t h1 = packh2(x.w, x.z);
        *(uint2*)((char*)d_Ah + (base + off) * 2) = make_uint2(h0, h1);
    }
    red[t] = acc;
    __syncthreads();
    for (int s = 128; s > 0; s >>= 1) {
        if (t < s) red[t] += red[t + s];
        __syncthreads();
    }
    if (t == 0) d_p1p[fv * 64 + ec] = red[0];
}

// ---------------- K4: main mma.sync GEMM -------------------------------------------
// CTA 128(E) x 128(N); 16 warps = 4(m) x 4(n); warp 32x32.
// k-chunks of 64 (128B rows, ROWB=144), 8 chunks, 3 stages.
#define ROWB 144
#define MATB 18432
#define STAGEB 55296

__global__ void __launch_bounds__(512, 1)
k_gemm(float* __restrict__ out) {
    extern __shared__ __align__(16) char dsm[];
    uint32_t sb = smem_to_u32(dsm);
    int t = threadIdx.x;
    int wid = t >> 5, lane = t & 31;
    int wm = wid & 3, wn = wid >> 2;
    int fv = blockIdx.z, e0 = blockIdx.y * 128, n0 = blockIdx.x * 128;

    const char* gA = (const char*)d_Ah + ((size_t)fv * E_ + e0) * NI * 2;
    const char* gB = (const char*)d_Bw + ((size_t)fv * NO + n0) * NI * 2;
    const char* gH = (const char*)d_Hb + ((size_t)fv * NO + n0) * NI * 2;

    // loader: per matrix 1024 16B segments; thread does segs t and t+512
    auto load_chunk = [&](int c, uint32_t base) {
#pragma unroll
        for (int it = 0; it < 2; it++) {
            int seg = t + it * 512;
            int row = seg >> 3, j = seg & 7;
            uint32_t s = base + row * ROWB + j * 16;
            size_t g = (size_t)row * 1024 + (size_t)c * 128 + j * 16;
            cp_async16(s,            gA + g);
            cp_async16(s + MATB,     gB + g);
            cp_async16(s + 2 * MATB, gH + g);
        }
    };

    float zc[2][4][4], uc[2][4][4];
#pragma unroll
    for (int i = 0; i < 2; i++)
#pragma unroll
        for (int j = 0; j < 4; j++)
#pragma unroll
            for (int k = 0; k < 4; k++) { zc[i][j][k] = 0.f; uc[i][j][k] = 0.f; }

    uint32_t aoff = (wm * 32 + (lane & 15)) * ROWB + (lane >> 4) * 16;
    uint32_t boff = (wn * 32 + (lane & 15)) * ROWB + (lane >> 4) * 16;

    load_chunk(0, sb);          CP_COMMIT();
    load_chunk(1, sb + STAGEB); CP_COMMIT();

    for (int c = 0; c < 8; c++) {
        uint32_t base = sb + (uint32_t)(c % 3) * STAGEB;
        if (c < 7) { CP_WAIT1(); } else { CP_WAIT0(); }
        __syncthreads();
        if (c + 2 < 8) {
            load_chunk(c + 2, sb + (uint32_t)((c + 2) % 3) * STAGEB);
            CP_COMMIT();
        }
#pragma unroll
        for (int ks = 0; ks < 4; ks++) {
            uint32_t ah[2][4];
#pragma unroll
            for (int mt = 0; mt < 2; mt++)
                ldm4(ah[mt], base + aoff + mt * (16 * ROWB) + ks * 32);
            uint32_t bw[2][4], hb[2][4];
#pragma unroll
            for (int pp = 0; pp < 2; pp++) {
                uint32_t bd = base + MATB + boff + pp * (16 * ROWB) + ks * 32;
                ldm4(bw[pp], bd);
                ldm4(hb[pp], bd + MATB);
            }
#pragma unroll
            for (int mt = 0; mt < 2; mt++)
#pragma unroll
                for (int nt = 0; nt < 4; nt++) {
                    int pp = nt >> 1, s = nt & 1;
                    mma_f16(zc[mt][nt], ah[mt], bw[pp][s], bw[pp][s + 2]);
                    mma_f16(uc[mt][nt], ah[mt], hb[pp][s], hb[pp][s + 2]);
                }
        }
    }

    // ---------------- epilogue ----------------
    float pw = 0.f;
    int lrow = lane >> 2, lcol = (lane & 3) * 2;
#pragma unroll
    for (int nt = 0; nt < 4; nt++) {
        int nc = n0 + wn * 32 + nt * 8 + lcol;
        float fz0 = d_fixz[fv * NO + nc],     fz1 = d_fixz[fv * NO + nc + 1];
        float fu0 = d_fixu[fv * NO + nc],     fu1 = d_fixu[fv * NO + nc + 1];
        float G0  = d_G[nc],                  G1  = d_G[nc + 1];
        float4 P0 = d_actp[nc],               P1  = d_actp[nc + 1];
#pragma unroll
        for (int mt = 0; mt < 2; mt++) {
            int r0 = e0 + wm * 32 + mt * 16 + lrow;
#pragma unroll
            for (int h = 0; h < 2; h++) {
                float z0 = zc[mt][nt][2 * h + 0] + fz0;
                float z1 = zc[mt][nt][2 * h + 1] + fz1;
                float u0 = uc[mt][nt][2 * h + 0] + fu0;
                float u1 = uc[mt][nt][2 * h + 1] + fu1;
                pw += z0 * (z0 * G0 - 2.f * u0);
                pw += z1 * (z1 * G1 - 2.f * u1);
                float2 o;
                o.x = P0.x + P0.y * tanhf((z0 - P0.z) * P0.w);
                o.y = P1.x + P1.y * tanhf((z1 - P1.z) * P1.w);
                *(float2*)(out + ((size_t)fv * E_ + r0 + h * 8) * NO + nc) = o;
            }
        }
    }

    __shared__ float red[512];
    red[t] = pw;
    __syncthreads();
    for (int s = 256; s > 0; s >>= 1) {
        if (t < s) red[t] += red[t + s];
        __syncthreads();
    }
    if (t == 0)
        d_pwp[(blockIdx.z * 4 + blockIdx.x) * 16 + blockIdx.y] = red[0];
}

// ---------------- K5: final --------------------------------------------------------
__global__ void k_final(float* __restrict__ out, int out_size) {
    __shared__ float red[256];
    int t = threadIdx.x;
    float s = 0.f;
    for (int i = t; i < 512; i += 256) s += d_pwp[i];
    for (int i = t; i < FV * 64; i += 256) s += d_p1p[i];
    red[t] = s;
    __syncthreads();
    for (int k = 128; k > 0; k >>= 1) {
        if (t < k) red[t] += red[t + k];
        __syncthreads();
    }
    if (t == 0) {
        float p1_ones = (float)(FV * E_) * d_gsumm[512];
        float power = (red[0] + p1_ones) / (float)(E_ * V_ * F_);
        long long total = (long long)FV * E_ * NO;
        if (out_size > total) out[total] = power;
    }
}

extern "C" void kernel_launch(void* const* d_in, const int* in_sizes, int n_in,
                              void* d_out, int out_size) {
    const float* a     = (const float*)d_in[0];
    const float* theta = (const float*)d_in[1];
    const float* coef  = (const float*)d_in[2];
    const float* nu    = (const float*)d_in[3];
    const float* gum   = (const float*)d_in[4];
    float* out = (float*)d_out;
    (void)in_sizes; (void)n_in;

    static int smem_set = 0;
    if (!smem_set) {
        cudaFuncSetAttribute(k_gemm, cudaFuncAttributeMaxDynamicSharedMemorySize,
                             3 * STAGEB);
        smem_set = 1;
    }

    k_pre1<<<576, 256>>>(theta, coef, gum, nu);
    k_pre2<<<dim3(8, 8, 9), 256>>>(theta, nu);
    k_prepA<<<dim3(64, FV), 256>>>(a);
    k_gemm<<<dim3(4, 16, FV), 512, 3 * STAGEB>>>(out);
    k_final<<<1, 256>>>(out, out_size);
}

// round 11
// speedup vs baseline: 1.2908x; 1.0415x over previous
#include <cuda_runtime.h>
#include <cuda_fp16.h>
#include <math.h>
#include <stdint.h>

#define F_ 2
#define V_ 4
#define FV 8
#define E_ 2048
#define NI 512
#define NO 512
#define M_ 514
#define GMIN 0.01f
#define GMAX 10.0f
#define PGMIN 1e-4f

// ---------------- scratch ------------------------------------------------------
__device__ __align__(16) unsigned short d_Ah[FV * E_ * NI];   // x fp16 [fv][e][k]
__device__ __align__(16) unsigned short d_Bw[FV * NO * NI];   // W fp16 [fv][n][k]
__device__ __align__(16) unsigned short d_Hb[FV * NO * NI];   // H fp16 [fv][n][k]
__device__ float d_gtilde[M_ * NO];
__device__ float d_G[NO];
__device__ float d_gsumm[M_];
__device__ float d_denp[FV * 32 * NO];
__device__ float d_fixz[FV * NO];
__device__ float d_fixu[FV * NO];
__device__ float4 d_actp[NO];
__device__ __align__(16) float d_s2p[512 * 512];   // per conv-block x^2 column sums
__device__ float d_pwp[512];

__constant__ float c_etas[16] = {
    0.05f, 0.90f, 0.20f, 8.0f,
    0.10f, 0.80f, 0.30f, 5.0f,
    0.00f, 1.00f, 0.25f, 10.0f,
    0.15f, 0.70f, 0.15f, 6.0f};

__device__ __forceinline__ float th_clip(float t) {
    return fminf(fmaxf(t, -GMAX), GMAX);
}
__device__ __forceinline__ float th_fwd(float t) {
    float c = th_clip(t);
    return (fabsf(c) < GMIN) ? 0.0f : c;
}

// ---------------- PTX helpers (base ISA only) -----------------------------------
__device__ __forceinline__ uint32_t smem_to_u32(const void* p) {
    uint32_t a;
    asm("{ .reg .u64 t; cvta.to.shared.u64 t, %1; cvt.u32.u64 %0, t; }" : "=r"(a) : "l"(p));
    return a;
}
__device__ __forceinline__ uint32_t packh2(float hi, float lo) {
    uint32_t r;
    asm("cvt.rn.f16x2.f32 %0, %1, %2;" : "=r"(r) : "f"(hi), "f"(lo));
    return r;
}
__device__ __forceinline__ void cp_async16(uint32_t s, const void* g) {
    asm volatile("cp.async.cg.shared.global [%0], [%1], 16;" :: "r"(s), "l"(g) : "memory");
}
#define CP_COMMIT() asm volatile("cp.async.commit_group;" ::: "memory")
#define CP_WAIT1()  asm volatile("cp.async.wait_group 1;" ::: "memory")
#define CP_WAIT0()  asm volatile("cp.async.wait_group 0;" ::: "memory")

__device__ __forceinline__ void ldm4(uint32_t r[4], uint32_t addr) {
    asm volatile("ldmatrix.sync.aligned.m8n8.x4.shared.b16 {%0,%1,%2,%3}, [%4];"
                 : "=r"(r[0]), "=r"(r[1]), "=r"(r[2]), "=r"(r[3]) : "r"(addr));
}
__device__ __forceinline__ void mma_f16(float c[4], const uint32_t a[4],
                                        uint32_t b0, uint32_t b1) {
    asm volatile(
        "mma.sync.aligned.m16n8k16.row.col.f32.f16.f16.f32 "
        "{%0,%1,%2,%3}, {%4,%5,%6,%7}, {%8,%9}, {%0,%1,%2,%3};"
        : "+f"(c[0]), "+f"(c[1]), "+f"(c[2]), "+f"(c[3])
        : "r"(a[0]), "r"(a[1]), "r"(a[2]), "r"(a[3]), "r"(b0), "r"(b1));
}

// ---------------- K1: denp (0..511) + gtilde/G/act (512..575) + A conv (576..1087)
__global__ void k_pre1(const float* __restrict__ theta,
                       const float* __restrict__ coef,
                       const float* __restrict__ gum,
                       const float* __restrict__ nu,
                       const float* __restrict__ a) {
    int b = blockIdx.x;
    int t = threadIdx.x;
    if (b < 512) {
        int bx = b & 31;
        int yy = (b >> 5) & 1;
        int fv = b >> 6;
        int n = yy * 256 + t;
        int m0 = bx * 17, m1 = min(M_, m0 + 17);
        float acc = 0.f;
#pragma unroll 17
        for (int m = m0; m < m1; m++) {
            float th = th_fwd(theta[m * NO + n]);
            float u = nu[((size_t)fv * M_ + m) * NO + n];
            acc += fabsf(th * (u * 0.2f + 0.9f));
        }
        d_denp[((size_t)fv * 32 + bx) * NO + n] = acc;
    } else if (b < 576) {
        int blk = b - 512;
        int w = t >> 5, lane = t & 31;
        int n = blk * 8 + w;
        float mn = 1e30f;
#pragma unroll
        for (int i = 0; i < 17; i++) {
            int m = lane + 32 * i;
            if (m < M_) mn = fminf(mn, fabsf(th_clip(theta[m * NO + n])));
        }
#pragma unroll
        for (int s = 16; s > 0; s >>= 1)
            mn = fminf(mn, __shfl_xor_sync(0xFFFFFFFFu, mn, s));
        float scale = PGMIN / mn;
        float sum = 0.f;
#pragma unroll
        for (int i = 0; i < 17; i++) {
            int m = lane + 32 * i;
            if (m < M_) {
                float g = fabsf(th_clip(theta[m * NO + n])) * scale;
                d_gtilde[m * NO + n] = g;
                sum += g;
            }
        }
#pragma unroll
        for (int s = 16; s > 0; s >>= 1)
            sum += __shfl_xor_sync(0xFFFFFFFFu, sum, s);
        if (lane == 0) {
            d_G[n] = sum;
            float best = -1e30f;
            int bi = 0;
#pragma unroll
            for (int i = 0; i < 4; i++) {
                float c = fminf(fmaxf(coef[i * NO + n], -1.f), 1.f);
                float g = gum[i * NO + n];
                float gn = -logf(-logf(g + 1e-20f) + 1e-20f);
                float v = c + gn;
                if (v > best) { best = v; bi = i; }
            }
            d_actp[n] = make_float4(c_etas[bi * 4 + 0], c_etas[bi * 4 + 1],
                                    c_etas[bi * 4 + 2], c_etas[bi * 4 + 3]);
        }
    } else {
        // A conversion (32 E-rows) + per-block x^2 column partials
        int idx = b - 576;              // 0..511
        int ec = idx & 63, fv = idx >> 6;
        size_t base = ((size_t)fv * E_ + ec * 32) * NI;
        const float* ab = a + base;
        int c4 = t & 127;
        float4 acc4 = make_float4(0.f, 0.f, 0.f, 0.f);
#pragma unroll 4
        for (int j = 0; j < 16; j++) {
            int e = 2 * j + (t >> 7);
            size_t off = (size_t)e * NI + c4 * 4;
            float4 x = *(const float4*)(ab + off);
            acc4.x += x.x * x.x;
            acc4.y += x.y * x.y;
            acc4.z += x.z * x.z;
            acc4.w += x.w * x.w;
            uint32_t h0 = packh2(x.y, x.x);
            uint32_t h1 = packh2(x.w, x.z);
            *(uint2*)((char*)d_Ah + (base + off) * 2) = make_uint2(h0, h1);
        }
        __shared__ float4 s4[128];
        if (t >= 128) s4[c4] = acc4;
        __syncthreads();
        if (t < 128) {
            float4 o = s4[c4];
            acc4.x += o.x; acc4.y += o.y; acc4.z += o.z; acc4.w += o.w;
            *(float4*)&d_s2p[(size_t)idx * 512 + c4 * 4] = acc4;
        }
    }
}

// ---------------- K2: prepB (z<8, inline invden + fix on x==0) + gsumm (z==8) ----
__global__ void k_pre2(const float* __restrict__ theta, const float* __restrict__ nu) {
    int t = threadIdx.x;
    if (blockIdx.z == 8) {
        int idx = blockIdx.y * 8 + blockIdx.x;
        int w = t >> 5, lane = t & 31;
#pragma unroll
        for (int rep = 0; rep < 2; rep++) {
            int j = w + 8 * rep;
            int r = idx * 9 + j;
            if (j < 9 && r < M_) {
                float s = 0.f;
#pragma unroll
                for (int i = 0; i < 16; i++)
                    s += d_gtilde[r * NO + lane + 32 * i];
#pragma unroll
                for (int q = 16; q > 0; q >>= 1)
                    s += __shfl_xor_sync(0xFFFFFFFFu, s, q);
                if (lane == 0) d_gsumm[r] = s;
            }
        }
        return;
    }
    __shared__ float sw[64][65], sh[64][65];
    int mt = blockIdx.x * 64, nt = blockIdx.y * 64, fv = blockIdx.z;
    int nl = t & 63;
    float den = 1e-10f;
#pragma unroll
    for (int i = 0; i < 32; i++)
        den += d_denp[((size_t)fv * 32 + i) * NO + nt + nl];
    float inv = 1.f / den;
#pragma unroll 4
    for (int r = 0; r < 16; r++) {
        int ml = (t >> 6) * 16 + r;
        int m = mt + ml, n = nt + nl;
        float th = th_fwd(theta[m * NO + n]);
        float u = nu[((size_t)fv * M_ + m) * NO + n];
        float w = th * (u * 0.2f + 0.9f) * inv;
        sw[ml][nl] = w;
        sh[ml][nl] = d_gtilde[m * NO + n] * (w >= 0.f ? 1.f : -1.f);
    }
    if (blockIdx.x == 0 && t < 64) {
        int n = nt + t;
        float th = th_fwd(theta[512 * NO + n]);
        float u = nu[((size_t)fv * M_ + 512) * NO + n];
        float tn = th * (u * 0.2f + 0.9f);
        d_fixz[fv * NO + n] = tn * inv;
        d_fixu[fv * NO + n] = d_gtilde[512 * NO + n] * (tn >= 0.f ? 1.f : -1.f);
    }
    __syncthreads();
    int nr = t >> 2, q = t & 3;
#pragma unroll
    for (int hf = 0; hf < 2; hf++) {
        float wv[8], hv[8];
#pragma unroll
        for (int j = 0; j < 8; j++) {
            wv[j] = sw[q * 16 + hf * 8 + j][nr];
            hv[j] = sh[q * 16 + hf * 8 + j][nr];
        }
        uint32_t hw[4], hb[4];
#pragma unroll
        for (int p = 0; p < 4; p++) {
            hw[p] = packh2(wv[2 * p + 1], wv[2 * p]);
            hb[p] = packh2(hv[2 * p + 1], hv[2 * p]);
        }
        size_t eoff = ((size_t)fv * NO + nt + nr) * NI + mt + q * 16 + hf * 8;
        *(uint4*)((char*)d_Bw + eoff * 2) = make_uint4(hw[0], hw[1], hw[2], hw[3]);
        *(uint4*)((char*)d_Hb + eoff * 2) = make_uint4(hb[0], hb[1], hb[2], hb[3]);
    }
}

// ---------------- K3: main mma.sync GEMM -------------------------------------------
// CTA 128(E) x 128(N); 16 warps = 4(m) x 4(n); warp 32x32.
// k-chunks of 64 (128B rows, ROWB=144), 8 chunks, 3 stages.
#define ROWB 144
#define MATB 18432
#define STAGEB 55296

__global__ void __launch_bounds__(512, 1)
k_gemm(float* __restrict__ out) {
    extern __shared__ __align__(16) char dsm[];
    uint32_t sb = smem_to_u32(dsm);
    int t = threadIdx.x;
    int wid = t >> 5, lane = t & 31;
    int wm = wid & 3, wn = wid >> 2;
    int fv = blockIdx.z, e0 = blockIdx.y * 128, n0 = blockIdx.x * 128;

    const char* gA = (const char*)d_Ah + ((size_t)fv * E_ + e0) * NI * 2;
    const char* gB = (const char*)d_Bw + ((size_t)fv * NO + n0) * NI * 2;
    const char* gH = (const char*)d_Hb + ((size_t)fv * NO + n0) * NI * 2;

    auto load_chunk = [&](int c, uint32_t base) {
#pragma unroll
        for (int it = 0; it < 2; it++) {
            int seg = t + it * 512;
            int row = seg >> 3, j = seg & 7;
            uint32_t s = base + row * ROWB + j * 16;
            size_t g = (size_t)row * 1024 + (size_t)c * 128 + j * 16;
            cp_async16(s,            gA + g);
            cp_async16(s + MATB,     gB + g);
            cp_async16(s + 2 * MATB, gH + g);
        }
    };

    float zc[2][4][4], uc[2][4][4];
#pragma unroll
    for (int i = 0; i < 2; i++)
#pragma unroll
        for (int j = 0; j < 4; j++)
#pragma unroll
            for (int k = 0; k < 4; k++) { zc[i][j][k] = 0.f; uc[i][j][k] = 0.f; }

    uint32_t aoff = (wm * 32 + (lane & 15)) * ROWB + (lane >> 4) * 16;
    uint32_t boff = (wn * 32 + (lane & 15)) * ROWB + (lane >> 4) * 16;

    load_chunk(0, sb);          CP_COMMIT();
    load_chunk(1, sb + STAGEB); CP_COMMIT();

    for (int c = 0; c < 8; c++) {
        uint32_t base = sb + (uint32_t)(c % 3) * STAGEB;
        if (c < 7) { CP_WAIT1(); } else { CP_WAIT0(); }
        __syncthreads();
        if (c + 2 < 8) {
            load_chunk(c + 2, sb + (uint32_t)((c + 2) % 3) * STAGEB);
            CP_COMMIT();
        }
#pragma unroll
        for (int ks = 0; ks < 4; ks++) {
            uint32_t ah[2][4];
#pragma unroll
            for (int mt = 0; mt < 2; mt++)
                ldm4(ah[mt], base + aoff + mt * (16 * ROWB) + ks * 32);
            uint32_t bw[2][4], hb[2][4];
#pragma unroll
            for (int pp = 0; pp < 2; pp++) {
                uint32_t bd = base + MATB + boff + pp * (16 * ROWB) + ks * 32;
                ldm4(bw[pp], bd);
                ldm4(hb[pp], bd + MATB);
            }
#pragma unroll
            for (int mt = 0; mt < 2; mt++)
#pragma unroll
                for (int nt = 0; nt < 4; nt++) {
                    int pp = nt >> 1, s = nt & 1;
                    mma_f16(zc[mt][nt], ah[mt], bw[pp][s], bw[pp][s + 2]);
                    mma_f16(uc[mt][nt], ah[mt], hb[pp][s], hb[pp][s + 2]);
                }
        }
    }

    // ---------------- epilogue ----------------
    float pw = 0.f;
    int lrow = lane >> 2, lcol = (lane & 3) * 2;
#pragma unroll
    for (int nt = 0; nt < 4; nt++) {
        int nc = n0 + wn * 32 + nt * 8 + lcol;
        float fz0 = d_fixz[fv * NO + nc],     fz1 = d_fixz[fv * NO + nc + 1];
        float fu0 = d_fixu[fv * NO + nc],     fu1 = d_fixu[fv * NO + nc + 1];
        float G0  = d_G[nc],                  G1  = d_G[nc + 1];
        float4 P0 = d_actp[nc],               P1  = d_actp[nc + 1];
#pragma unroll
        for (int mt = 0; mt < 2; mt++) {
            int r0 = e0 + wm * 32 + mt * 16 + lrow;
#pragma unroll
            for (int h = 0; h < 2; h++) {
                float z0 = zc[mt][nt][2 * h + 0] + fz0;
                float z1 = zc[mt][nt][2 * h + 1] + fz1;
                float u0 = uc[mt][nt][2 * h + 0] + fu0;
                float u1 = uc[mt][nt][2 * h + 1] + fu1;
                pw += z0 * (z0 * G0 - 2.f * u0);
                pw += z1 * (z1 * G1 - 2.f * u1);
                float2 o;
                o.x = P0.x + P0.y * tanhf((z0 - P0.z) * P0.w);
                o.y = P1.x + P1.y * tanhf((z1 - P1.z) * P1.w);
                *(float2*)(out + ((size_t)fv * E_ + r0 + h * 8) * NO + nc) = o;
            }
        }
    }

    // fold in p1 partial: this CTA reduces one conversion block's s2p row
    int gid = (blockIdx.z * 16 + blockIdx.y) * 4 + blockIdx.x;   // 0..511
    pw += d_s2p[(size_t)gid * 512 + t] * d_gsumm[t];

    __shared__ float red[512];
    red[t] = pw;
    __syncthreads();
    for (int s = 256; s > 0; s >>= 1) {
        if (t < s) red[t] += red[t + s];
        __syncthreads();
    }
    if (t == 0)
        d_pwp[gid] = red[0];
}

// ---------------- K4: final --------------------------------------------------------
__global__ void k_final(float* __restrict__ out, int out_size) {
    __shared__ float red[256];
    int t = threadIdx.x;
    float s = 0.f;
    for (int i = t; i < 512; i += 256) s += d_pwp[i];
    red[t] = s;
    __syncthreads();
    for (int k = 128; k > 0; k >>= 1) {
        if (t < k) red[t] += red[t + k];
        __syncthreads();
    }
    if (t == 0) {
        float p1_ones = (float)(FV * E_) * d_gsumm[512];
        float power = (red[0] + p1_ones) / (float)(E_ * V_ * F_);
        long long total = (long long)FV * E_ * NO;
        if (out_size > total) out[total] = power;
    }
}

extern "C" void kernel_launch(void* const* d_in, const int* in_sizes, int n_in,
                              void* d_out, int out_size) {
    const float* a     = (const float*)d_in[0];
    const float* theta = (const float*)d_in[1];
    const float* coef  = (const float*)d_in[2];
    const float* nu    = (const float*)d_in[3];
    const float* gum   = (const float*)d_in[4];
    float* out = (float*)d_out;
    (void)in_sizes; (void)n_in;

    static int smem_set = 0;
    if (!smem_set) {
        cudaFuncSetAttribute(k_gemm, cudaFuncAttributeMaxDynamicSharedMemorySize,
                             3 * STAGEB);
        smem_set = 1;
    }

    k_pre1<<<1088, 256>>>(theta, coef, gum, nu, a);
    k_pre2<<<dim3(8, 8, 9), 256>>>(theta, nu);
    k_gemm<<<dim3(4, 16, FV), 512, 3 * STAGEB>>>(out);
    k_final<<<1, 256>>>(out, out_size);
}